// round 11
// baseline (speedup 1.0000x reference)
#include <cuda_runtime.h>
#include <math.h>

#define H 256
#define DIN 700
#define DOUT 20
#define BATCH 128
#define TT 250

// Scratch (device globals: allocation-free rule).
// g_X1 is T-MAJOR: X1[t][b][i]. Weight tables have zero row 256 for pads.
__device__ float g_X1[(size_t)TT * BATCH * H];
__device__ float g_W11T[(H + 1) * H];
__device__ float g_W12T[(H + 1) * H];
__device__ float g_W22T[(H + 1) * H];
__device__ int   g_ready[TT];      // 4 == timestep t of X1 complete (4 CTAs/t)

// ---------------------------------------------------------------------------
__device__ __forceinline__ void ffma2(unsigned long long& acc,
                                      unsigned long long a,
                                      unsigned long long b) {
    asm("fma.rn.f32x2 %0, %1, %2, %0;" : "+l"(acc) : "l"(a), "l"(b));
}
__device__ __forceinline__ unsigned long long pack2(float lo, float hi) {
    unsigned long long r;
    asm("mov.b64 %0, {%1, %2};" : "=l"(r) : "f"(lo), "f"(hi));
    return r;
}
__device__ __forceinline__ void unpack2(unsigned long long v, float& lo, float& hi) {
    asm("mov.b64 {%0, %1}, %2;" : "=f"(lo), "=f"(hi) : "l"(v));
}
__device__ __forceinline__ int ld_acquire(const int* p) {
    int v;
    asm volatile("ld.acquire.gpu.b32 %0, [%1];" : "=r"(v) : "l"(p) : "memory");
    return v;
}

// ---------------------------------------------------------------------------
__global__ void clear_flags_kernel() {
    int i = threadIdx.x + blockIdx.x * blockDim.x;
    if (i < TT) g_ready[i] = 0;
}

// ---------------------------------------------------------------------------
__global__ void transpose_weights_kernel(const float* __restrict__ W11,
                                         const float* __restrict__ W12,
                                         const float* __restrict__ W22) {
    int idx = blockIdx.x * blockDim.x + threadIdx.x;
    if (idx < 3 * H * H) {
        int m = idx >> 16;
        int r = (idx >> 8) & 255;
        int c = idx & 255;
        if (m == 0)      g_W11T[c * H + r] = W11[r * H + c];
        else if (m == 1) g_W12T[c * H + r] = W12[r * H + c];
        else             g_W22T[c * H + r] = W22[r * H + c];
    } else {
        int w = idx - 3 * H * H;
        if (w < 3 * H) {
            int m = w >> 8, c = w & 255;
            if (m == 0)      g_W11T[256 * H + c] = 0.f;
            else if (m == 1) g_W12T[256 * H + c] = 0.f;
            else             g_W22T[256 * H + c] = 0.f;
        }
    }
}

// ---------------------------------------------------------------------------
// X1[t][b][:] = x[b][t][:] @ Wi1.T + (bi1 + b11).
// SMALL-CTA version for co-residency with rnn_kernel on the same SM:
// 128 threads, <=128 regs (16.4K regs/CTA), 25.6KB smem. Tile 64x128,
// grid (4, TT): blockIdx.x = {mtile, ntile}, blockIdx.y = timestep.
// Publishes g_ready[t] with 4 arrivals.
// ---------------------------------------------------------------------------
#define GBK 16
#define GPAD 4
#define GNT ((DIN + GBK - 1) / GBK)

__global__ __launch_bounds__(128, 4) void gemm_x1_kernel(
    const float* __restrict__ x, const float* __restrict__ Wi1,
    const float* __restrict__ bi1, const float* __restrict__ b11) {
    __shared__ float As[2][GBK][64 + GPAD];
    __shared__ float Bs[2][GBK][128 + GPAD];

    int tid = threadIdx.x;
    int tstep = blockIdx.y;
    int b0 = (blockIdx.x & 1) * 64;        // sample tile
    int n0 = (blockIdx.x >> 1) * 128;      // neuron tile
    int tx = tid & 15, ty = tid >> 4;      // 16 x 8 thread tile (8x8 outputs)

    int rowX0 = tid >> 2, kc = tid & 3;    // A: rows 0..31 (it=0), 32..63 (it=1)
    int rowX1 = (128 + tid) >> 2;
    // B rows: (it*128 + tid) >> 2 for it = 0..3 -> 0..127

    const float* xr0 = x + ((size_t)(b0 + rowX0) * TT + tstep) * DIN;
    const float* xr1 = x + ((size_t)(b0 + rowX1) * TT + tstep) * DIN;

    unsigned long long acc[4][8];
#pragma unroll
    for (int r = 0; r < 4; ++r)
#pragma unroll
        for (int c = 0; c < 8; ++c) acc[r][c] = 0ull;

    float4 sA0, sA1, sB[4];

    // prologue: tile 0
    {
        int kA = kc * 4;
        sA0 = *(const float4*)(xr0 + kA);
        sA1 = *(const float4*)(xr1 + kA);
#pragma unroll
        for (int it = 0; it < 4; ++it) {
            int rowB = (it * 128 + tid) >> 2;
            sB[it] = *(const float4*)(Wi1 + (size_t)(n0 + rowB) * DIN + kA);
        }
        As[0][kc * 4 + 0][rowX0] = sA0.x; As[0][kc * 4 + 1][rowX0] = sA0.y;
        As[0][kc * 4 + 2][rowX0] = sA0.z; As[0][kc * 4 + 3][rowX0] = sA0.w;
        As[0][kc * 4 + 0][rowX1] = sA1.x; As[0][kc * 4 + 1][rowX1] = sA1.y;
        As[0][kc * 4 + 2][rowX1] = sA1.z; As[0][kc * 4 + 3][rowX1] = sA1.w;
#pragma unroll
        for (int it = 0; it < 4; ++it) {
            int rowB = (it * 128 + tid) >> 2;
            Bs[0][kc * 4 + 0][rowB] = sB[it].x; Bs[0][kc * 4 + 1][rowB] = sB[it].y;
            Bs[0][kc * 4 + 2][rowB] = sB[it].z; Bs[0][kc * 4 + 3][rowB] = sB[it].w;
        }
    }
    __syncthreads();

    for (int t = 0; t < GNT; ++t) {
        int buf = t & 1;

        if (t + 1 < GNT) {
            int kA = (t + 1) * GBK + kc * 4;
            bool ok = kA < DIN;
            sA0 = ok ? *(const float4*)(xr0 + kA) : make_float4(0.f,0.f,0.f,0.f);
            sA1 = ok ? *(const float4*)(xr1 + kA) : make_float4(0.f,0.f,0.f,0.f);
#pragma unroll
            for (int it = 0; it < 4; ++it) {
                int rowB = (it * 128 + tid) >> 2;
                sB[it] = ok ? *(const float4*)(Wi1 + (size_t)(n0 + rowB) * DIN + kA)
                            : make_float4(0.f, 0.f, 0.f, 0.f);
            }
        }

#pragma unroll
        for (int kk = 0; kk < GBK; ++kk) {
            ulonglong2 aA = *(const ulonglong2*)&As[buf][kk][ty * 8];
            ulonglong2 aB = *(const ulonglong2*)&As[buf][kk][ty * 8 + 4];
            float4 b0v = *(const float4*)&Bs[buf][kk][tx * 8];
            float4 b1v = *(const float4*)&Bs[buf][kk][tx * 8 + 4];
            float barr[8] = {b0v.x, b0v.y, b0v.z, b0v.w, b1v.x, b1v.y, b1v.z, b1v.w};
#pragma unroll
            for (int c = 0; c < 8; ++c) {
                unsigned long long bb = pack2(barr[c], barr[c]);
                ffma2(acc[0][c], aA.x, bb);
                ffma2(acc[1][c], aA.y, bb);
                ffma2(acc[2][c], aB.x, bb);
                ffma2(acc[3][c], aB.y, bb);
            }
        }

        if (t + 1 < GNT) {
            int nb = buf ^ 1;
            As[nb][kc * 4 + 0][rowX0] = sA0.x; As[nb][kc * 4 + 1][rowX0] = sA0.y;
            As[nb][kc * 4 + 2][rowX0] = sA0.z; As[nb][kc * 4 + 3][rowX0] = sA0.w;
            As[nb][kc * 4 + 0][rowX1] = sA1.x; As[nb][kc * 4 + 1][rowX1] = sA1.y;
            As[nb][kc * 4 + 2][rowX1] = sA1.z; As[nb][kc * 4 + 3][rowX1] = sA1.w;
#pragma unroll
            for (int it = 0; it < 4; ++it) {
                int rowB = (it * 128 + tid) >> 2;
                Bs[nb][kc * 4 + 0][rowB] = sB[it].x; Bs[nb][kc * 4 + 1][rowB] = sB[it].y;
                Bs[nb][kc * 4 + 2][rowB] = sB[it].z; Bs[nb][kc * 4 + 3][rowB] = sB[it].w;
            }
        }
        __syncthreads();
    }

    float bias[8];
#pragma unroll
    for (int c = 0; c < 8; ++c) {
        int n = n0 + tx * 8 + c;
        bias[c] = bi1[n] + b11[n];
    }
    float* X1t = g_X1 + (size_t)tstep * BATCH * H;
#pragma unroll
    for (int r2 = 0; r2 < 4; ++r2) {
        float lo[8], hi[8];
#pragma unroll
        for (int c = 0; c < 8; ++c) unpack2(acc[r2][c], lo[c], hi[c]);
        int bA = b0 + ty * 8 + 2 * r2;
        int bB = bA + 1;
        int n = n0 + tx * 8;
        float4* pA = (float4*)(X1t + (size_t)bA * H + n);
        float4* pB = (float4*)(X1t + (size_t)bB * H + n);
        pA[0] = make_float4(lo[0] + bias[0], lo[1] + bias[1], lo[2] + bias[2], lo[3] + bias[3]);
        pA[1] = make_float4(lo[4] + bias[4], lo[5] + bias[5], lo[6] + bias[6], lo[7] + bias[7]);
        pB[0] = make_float4(hi[0] + bias[0], hi[1] + bias[1], hi[2] + bias[2], hi[3] + bias[3]);
        pB[1] = make_float4(hi[4] + bias[4], hi[5] + bias[5], hi[6] + bias[6], hi[7] + bias[7]);
    }

    __threadfence();
    __syncthreads();
    if (tid == 0) atomicAdd(&g_ready[tstep], 1);
}

// ---------------------------------------------------------------------------
__device__ __forceinline__ void acc4(const float* __restrict__ W,
                                     int4 j, int col, float4& h) {
    float4 v0 = *(const float4*)(W + j.x * H + col);
    float4 v1 = *(const float4*)(W + j.y * H + col);
    float4 v2 = *(const float4*)(W + j.z * H + col);
    float4 v3 = *(const float4*)(W + j.w * H + col);
    h.x += (v0.x + v1.x) + (v2.x + v3.x);
    h.y += (v0.y + v1.y) + (v2.y + v3.y);
    h.z += (v0.z + v1.z) + (v2.z + v3.z);
    h.w += (v0.w + v1.w) + (v2.w + v3.w);
}

// ---------------------------------------------------------------------------
// Persistent RNN: one CTA per sample, 512 threads, 4 barriers/step.
// __launch_bounds__(512, 2) hard-caps regs at 64 (== R7's measured natural
// usage) so rnn (32.8K regs) + gemm (16.4K) provably co-reside on one SM.
// Spins on g_ready[t] (4 producer CTAs per timestep).
// ---------------------------------------------------------------------------
__global__ __launch_bounds__(512, 2) void rnn_kernel(
    const float* __restrict__ mem1_0, const float* __restrict__ mem2_0,
    const float* __restrict__ memo_0,
    const float* __restrict__ b12v, const float* __restrict__ b22v,
    const float* __restrict__ Wo, const float* __restrict__ bov,
    const float* __restrict__ tau_adp1, const float* __restrict__ tau_adp2,
    const float* __restrict__ tau_m1, const float* __restrict__ tau_m2,
    const float* __restrict__ tau_mo,
    float* __restrict__ out) {
    __shared__ __align__(16) int list1[2][H];
    __shared__ __align__(16) int list2[2][H];
    __shared__ int cntp1[2][8], cntp2[2][8];   // padded per-segment counts
    __shared__ float part11[8][H];
    __shared__ float part22[8][H];
    __shared__ float part12[8][H];
    __shared__ float pout[8][32];
    __shared__ float sWoT[(H + 1) * DOUT];

    int b = blockIdx.x;
    int tid = threadIdx.x;
    int lane = tid & 31, warp = tid >> 5;
    int rep = tid >> 6;
    int slot = tid & 63;
    int col = slot << 2;

    for (int idx = tid; idx < H * DOUT; idx += 512) {
        int j = idx / DOUT, k = idx - j * DOUT;
        sWoT[idx] = Wo[k * H + j];
    }
    if (tid < DOUT) sWoT[H * DOUT + tid] = 0.f;
    if (tid < 8) {
        cntp1[0][tid] = 0; cntp1[1][tid] = 0;
        cntp2[0][tid] = 0; cntp2[1][tid] = 0;
    }

    float mem1 = 0.f, sp1 = 0.f, ab1 = 0.01f, al1 = 0.f, ro1 = 0.f;
    float mem2 = 0.f, sp2 = 0.f, ab2 = 0.01f, al2 = 0.f, ro2 = 0.f;
    float hb2 = 0.f;
    float memo = 0.f, alo = 0.f, omo = 0.f, bok = 0.f, accv = 0.f;
    if (tid < 256) {
        mem1 = mem1_0[b * H + tid];
        al1 = expf(-1.f / tau_m1[tid]);
        ro1 = expf(-1.f / tau_adp1[tid]);
        mem2 = mem2_0[b * H + tid];
        al2 = expf(-1.f / tau_m2[tid]);
        ro2 = expf(-1.f / tau_adp2[tid]);
        hb2 = b12v[tid] + b22v[tid];
        if (tid < DOUT) {
            memo = memo_0[b * DOUT + tid];
            alo = expf(-1.f / tau_mo[tid]); omo = 1.f - alo;
            bok = bov[tid];
        }
    }
    __syncthreads();

    int p = 0;

    float x1cur = 0.f;
    if (tid < 256) {
        while (ld_acquire(&g_ready[0]) < 4) __nanosleep(64);
        x1cur = g_X1[(size_t)b * H + tid];
    }

    for (int t = 0; t < TT; ++t) {
        int pn = p ^ 1;

        float x1nxt = 0.f;
        if (tid < 256 && t + 1 < TT) {
            while (ld_acquire(&g_ready[t + 1]) < 4) __nanosleep(64);
            x1nxt = g_X1[((size_t)(t + 1) * BATCH + b) * H + tid];
        }

        // ---- phase A: fused W11 (old sp1) + W22 (old sp2) segmented gather ----
        {
            float4 a11 = make_float4(0.f, 0.f, 0.f, 0.f);
            float4 a22 = make_float4(0.f, 0.f, 0.f, 0.f);
#pragma unroll
            for (int seg = 0; seg < 8; ++seg) {
                int ch = (rep + seg) & 7;        // rotated chunk assignment
                int c4 = ch << 2;
                int c1 = cntp1[p][seg];
                int c2 = cntp2[p][seg];
                const int4* s1 = (const int4*)&list1[p][seg << 5];
                const int4* s2 = (const int4*)&list2[p][seg << 5];
                if (c4 < c1) acc4(g_W11T, s1[ch], col, a11);
                if (c4 < c2) acc4(g_W22T, s2[ch], col, a22);
            }
            *(float4*)&part11[rep][col] = a11;
            *(float4*)&part22[rep][col] = a22;
        }
        __syncthreads();   // (a)

        // ---- layer 1 update + segmented list write (owners) ----
        if (tid < 256) {
            float h1 = x1cur;
#pragma unroll
            for (int r = 0; r < 8; ++r) h1 += part11[r][tid];
            ab1 = ro1 * ab1 + (1.f - ro1) * sp1;
            float B = 0.01f + 1.8f * ab1;
            mem1 = mem1 * al1 + (1.f - al1) * h1 - B * sp1;
            float sp1n = (mem1 - B) > 0.f ? 1.f : 0.f;
            unsigned bal = __ballot_sync(0xffffffffu, sp1n != 0.f);
            int cw = __popc(bal);
            int cwp = (cw + 3) & ~3;
            unsigned ltm = (1u << lane) - 1u;
            if (sp1n != 0.f) {
                list1[pn][(warp << 5) + __popc(bal & ltm)] = tid;
            } else {
                int np = __popc(~bal & ltm);
                if (np < cwp - cw) list1[pn][(warp << 5) + cw + np] = 256;
            }
            if (lane == 0) cntp1[pn][warp] = cwp;
            sp1 = sp1n;
        }
        __syncthreads();   // (b)

        // ---- phase B: W12 segmented gather (new sp1) ----
        {
            float4 a12 = make_float4(0.f, 0.f, 0.f, 0.f);
#pragma unroll
            for (int seg = 0; seg < 8; ++seg) {
                int ch = (rep + seg) & 7;        // rotated chunk assignment
                int c1 = cntp1[pn][seg];
                const int4* s1 = (const int4*)&list1[pn][seg << 5];
                if ((ch << 2) < c1) acc4(g_W12T, s1[ch], col, a12);
            }
            *(float4*)&part12[rep][col] = a12;
        }
        __syncthreads();   // (c)

        // ---- layer 2 update + list write + own-segment pout (owners) ----
        if (tid < 256) {
            float h2 = hb2;
#pragma unroll
            for (int r = 0; r < 8; ++r) h2 += part12[r][tid];
#pragma unroll
            for (int r = 0; r < 8; ++r) h2 += part22[r][tid];
            ab2 = ro2 * ab2 + (1.f - ro2) * sp2;
            float B = 0.01f + 1.8f * ab2;
            mem2 = mem2 * al2 + (1.f - al2) * h2 - B * sp2;
            float sp2n = (mem2 - B) > 0.f ? 1.f : 0.f;
            unsigned bal = __ballot_sync(0xffffffffu, sp2n != 0.f);
            int cw = __popc(bal);
            int cwp = (cw + 3) & ~3;
            unsigned ltm = (1u << lane) - 1u;
            if (sp2n != 0.f) {
                list2[pn][(warp << 5) + __popc(bal & ltm)] = tid;
            } else {
                int np = __popc(~bal & ltm);
                if (np < cwp - cw) list2[pn][(warp << 5) + cw + np] = 256;
            }
            if (lane == 0) cntp2[pn][warp] = cwp;
            sp2 = sp2n;

            // output partial for this warp's 32 neurons (ballot in register)
            int kk = lane < DOUT ? lane : 0;
            float o = 0.f;
            unsigned mm = bal;
            int jb = warp << 5;
            while (mm) {
                int l = __ffs(mm) - 1;
                mm &= mm - 1;
                o += sWoT[(jb + l) * DOUT + kk];
            }
            pout[warp][lane] = o;
        }
        __syncthreads();   // (d)

        // ---- output: warp 0 sums partials + softmax (others run ahead) ----
        if (warp == 0) {
            float o = bok;
#pragma unroll
            for (int g = 0; g < 8; ++g) o += pout[g][lane];
            memo = memo * alo + omo * o;
            float e = lane < DOUT ? __expf(memo) : 0.f;
            float ss = e;
#pragma unroll
            for (int sh = 16; sh > 0; sh >>= 1)
                ss += __shfl_xor_sync(0xffffffffu, ss, sh);
            if (t > 10) accv += e / ss;
        }

        p = pn;
        x1cur = x1nxt;
    }

    if (tid < DOUT) out[b * DOUT + tid] = accv;
}

// ---------------------------------------------------------------------------
// Overlapped launch. Liveness backstops: (1) rnn+gemm CTAs provably co-fit
// on one SM (49K regs, 75KB smem, 640 thr); (2) 128 rnn CTAs < 148 SMs
// leaves >=20 SMs free for gemm regardless. Producer launched first.
// ---------------------------------------------------------------------------
extern "C" void kernel_launch(void* const* d_in, const int* in_sizes, int n_in,
                              void* d_out, int out_size) {
    const float* x        = (const float*)d_in[0];
    const float* mem1_0   = (const float*)d_in[1];
    const float* mem2_0   = (const float*)d_in[2];
    const float* memo_0   = (const float*)d_in[3];
    const float* Wi1      = (const float*)d_in[4];
    const float* bi1      = (const float*)d_in[5];
    const float* W11      = (const float*)d_in[6];
    const float* b11      = (const float*)d_in[7];
    const float* W12      = (const float*)d_in[8];
    const float* b12      = (const float*)d_in[9];
    const float* W22      = (const float*)d_in[10];
    const float* b22      = (const float*)d_in[11];
    const float* Wo       = (const float*)d_in[12];
    const float* bo       = (const float*)d_in[13];
    const float* tau_adp1 = (const float*)d_in[14];
    const float* tau_adp2 = (const float*)d_in[15];
    const float* tau_m1   = (const float*)d_in[16];
    const float* tau_m2   = (const float*)d_in[17];
    const float* tau_mo   = (const float*)d_in[18];
    float* out = (float*)d_out;

    cudaStream_t s2 = 0;
    cudaEvent_t evFork = 0, evJoin = 0;
    bool forked =
        (cudaStreamCreateWithFlags(&s2, cudaStreamNonBlocking) == cudaSuccess) &&
        (cudaEventCreateWithFlags(&evFork, cudaEventDisableTiming) == cudaSuccess) &&
        (cudaEventCreateWithFlags(&evJoin, cudaEventDisableTiming) == cudaSuccess);

    clear_flags_kernel<<<1, 256>>>();
    transpose_weights_kernel<<<(3 * H * H + 3 * H + 255) / 256, 256>>>(W11, W12, W22);

    dim3 g(4, TT);   // {mtile,ntile} x timestep

    if (forked && cudaEventRecord(evFork, 0) == cudaSuccess &&
        cudaStreamWaitEvent(s2, evFork, 0) == cudaSuccess) {
        // Producer launched first; consumer co-resides and streams.
        gemm_x1_kernel<<<g, 128, 0, s2>>>(x, Wi1, bi1, b11);
        rnn_kernel<<<BATCH, 512>>>(mem1_0, mem2_0, memo_0, b12, b22, Wo, bo,
                                   tau_adp1, tau_adp2, tau_m1, tau_m2, tau_mo, out);
        cudaEventRecord(evJoin, s2);
        cudaStreamWaitEvent(0, evJoin, 0);
    } else {
        // Serial fallback: producer strictly before consumer.
        gemm_x1_kernel<<<g, 128>>>(x, Wi1, bi1, b11);
        rnn_kernel<<<BATCH, 512>>>(mem1_0, mem2_0, memo_0, b12, b22, Wo, bo,
                                   tau_adp1, tau_adp2, tau_m1, tau_m2, tau_mo, out);
    }

    if (evFork) cudaEventDestroy(evFork);
    if (evJoin) cudaEventDestroy(evJoin);
    if (s2) cudaStreamDestroy(s2);
}